// round 12
// baseline (speedup 1.0000x reference)
#include <cuda_runtime.h>
#include <math.h>

#define B_   128
#define S_   512
#define IN_  128
#define H_   512
#define C_   1000
#define NWRP 16           // warps per rnn block
#define HSPW 36           // per-warp Hs row pitch (floats), 16B-aligned

// Scratch (device globals: allocation-free per harness rules)
__device__ float g_xp [(size_t)B_ * S_ * H_];   // input projection (both layers)
__device__ float g_seq[(size_t)B_ * S_ * H_];   // layer-0 hidden sequence
__device__ float g_h  [2 * B_ * H_];            // double-buffered hidden state
__device__ unsigned g_flags[128];               // per-block warp-arrival flags (monotonic)

// ---------------- packed fp32x2 helpers (SASS FFMA2 path) -------------------
__device__ __forceinline__ unsigned long long pack2(float lo, float hi) {
    unsigned long long d;
    asm("mov.b64 %0, {%1, %2};" : "=l"(d)
        : "r"(__float_as_uint(lo)), "r"(__float_as_uint(hi)));
    return d;
}
__device__ __forceinline__ unsigned long long ffma2(
    unsigned long long a, unsigned long long b, unsigned long long c) {
    unsigned long long d;
    asm("fma.rn.f32x2 %0, %1, %2, %3;" : "=l"(d) : "l"(a), "l"(b), "l"(c));
    return d;
}
__device__ __forceinline__ unsigned long long fadd2(
    unsigned long long a, unsigned long long b) {
    unsigned long long d;
    asm("add.rn.f32x2 %0, %1, %2;" : "=l"(d) : "l"(a), "l"(b));
    return d;
}

// ---------------------------------------------------------------------------
// Persistent RNN layer, fine-grained producer->consumer flags, per-WARP
// release. Grid (8,16) = 128 blocks, 512 threads (16 warps). Block tile:
// 16 rows (m0 = bx*16) x 32 cols (n0 = by*32). Whh tile [512][32] resident in
// smem. Warp g consumes h k-slice [32g, 32g+32) = the full output tile of
// block (bx, by=g): it spin-waits (acquire) until that block's flag shows 16*t
// warp-arrivals, stages the slice, runs a 4x4 f32x2 microtile. Partials
// (16-way K-split) live in DOUBLE-BUFFERED smem so only ONE block barrier per
// step is needed (between partial-write and reduce-read). Each warp releases
// (+1, release semantics) right after its own epilogue stores, so block-
// internal skew pipelines across steps instead of re-synchronizing.
// Flags advance uniformly (+16*511 per launch) -> replay-safe; base is the
// block's own flag at launch.
// ---------------------------------------------------------------------------
__global__ void __launch_bounds__(512, 1) rnn_layer_kernel(
    const float* __restrict__ xp, const float* __restrict__ Wh,
    float* __restrict__ hA, float* __restrict__ hB,
    float* __restrict__ seqOut)
{
    extern __shared__ float sm[];
    float* Ws  = sm;                       // [512][32] k-major        (64 KB)
    float* Hs  = Ws + 512 * 32;            // 16 x [16][HSPW] per-warp (36 KB)
    float* Pr0 = Hs + NWRP * 16 * HSPW;    // [16][512] partials buf 0 (32 KB)
    float* Pr1 = Pr0 + NWRP * 512;         // [16][512] partials buf 1 (32 KB)
    __shared__ unsigned s_base;

    const int tid  = threadIdx.x;
    const int bx   = blockIdx.x;
    const int by   = blockIdx.y;
    const int m0   = bx << 4;             // 8 m-groups  -> 128 rows
    const int n0   = by << 5;             // 16 n-groups -> 512 cols
    const int g    = tid >> 5;            // warp = K-group 0..15
    const int lane = tid & 31;
    const int r0   = (lane >> 3) << 2;    // rows r0..r0+3
    const int c0   = (lane & 7) << 2;     // cols c0..c0+3
    const int kbeg = g << 5;              // 32 k per warp
    const int fi   = (bx << 4) + by;      // own flag index
    const int pfi  = (bx << 4) + g;       // producer flag for this warp
    float* HsW = Hs + g * (16 * HSPW);

    if (tid == 0) {
        unsigned cur;   // own flag: race-free base (only we increment it)
        asm volatile("ld.acquire.gpu.u32 %0, [%1];" : "=r"(cur) : "l"(&g_flags[fi]));
        s_base = cur;
    }

    // Load Whh tile once: Ws[k][n], n in [n0, n0+32), k in [0,512)
    for (int i = tid; i < 32 * 128; i += 512) {
        int n  = i & 31;
        int k4 = i >> 5;
        float4 v = *reinterpret_cast<const float4*>(
            &Wh[(size_t)(n0 + n) * H_ + (k4 << 2)]);
        int k = k4 << 2;
        Ws[(k + 0) * 32 + n] = v.x;
        Ws[(k + 1) * 32 + n] = v.y;
        Ws[(k + 2) * 32 + n] = v.z;
        Ws[(k + 3) * 32 + n] = v.w;
    }
    __syncthreads();
    const unsigned base = s_base;

    // Epilogue: warp g owns output row m0+g, lane = column
    const int er = g;                     // 0..15
    const int ec = lane;                  // 0..31

    const float* xrow = xp + ((size_t)(m0 + er) * S_) * H_ + n0 + ec;
    float xv = __ldg(xrow);               // t = 0

    for (int t = 0; t < S_; ++t) {
        const float* hp = (t & 1) ? hA : hB;
        float*       hn = (t & 1) ? hB : hA;
        float*       Pr = (t & 1) ? Pr1 : Pr0;

        float s = 0.f;

        if (t > 0) {
            // Wait for THIS warp's single producer block: 16*t warp-arrivals.
            if (lane == 0) {
                const unsigned need = (unsigned)(t << 4);
                unsigned cur;
                do {
                    asm volatile("ld.acquire.gpu.u32 %0, [%1];"
                                 : "=r"(cur) : "l"(&g_flags[pfi]));
                } while (cur - base < need);
            }
            __syncwarp();

            // Stage own k-slice: 16 rows x 32 k (warp-private region)
#pragma unroll
            for (int j = 0; j < 4; ++j) {
                int idx = lane + (j << 5);
                int r = idx >> 3, k4 = idx & 7;
                float4 v = __ldcg(reinterpret_cast<const float4*>(
                    &hp[(size_t)(m0 + r) * H_ + kbeg + (k4 << 2)]));
                *reinterpret_cast<float4*>(&HsW[r * HSPW + (k4 << 2)]) = v;
            }
            __syncwarp();

            unsigned long long a00 = 0, a01 = 0, a10 = 0, a11 = 0;
            unsigned long long a20 = 0, a21 = 0, a30 = 0, a31 = 0;

#pragma unroll
            for (int k4i = 0; k4i < 8; ++k4i) {
                const int kk = k4i << 2;
                float4 h0 = *reinterpret_cast<const float4*>(&HsW[(r0 + 0) * HSPW + kk]);
                float4 h1 = *reinterpret_cast<const float4*>(&HsW[(r0 + 1) * HSPW + kk]);
                float4 h2 = *reinterpret_cast<const float4*>(&HsW[(r0 + 2) * HSPW + kk]);
                float4 h3 = *reinterpret_cast<const float4*>(&HsW[(r0 + 3) * HSPW + kk]);
#define RNN_SUBK(ss, C)                                                        \
                {                                                              \
                    const ulonglong2 w = *reinterpret_cast<const ulonglong2*>( \
                        &Ws[(kbeg + kk + ss) * 32 + c0]);                      \
                    unsigned long long d;                                      \
                    d = pack2(h0.C, h0.C);                                     \
                    a00 = ffma2(d, w.x, a00); a01 = ffma2(d, w.y, a01);        \
                    d = pack2(h1.C, h1.C);                                     \
                    a10 = ffma2(d, w.x, a10); a11 = ffma2(d, w.y, a11);        \
                    d = pack2(h2.C, h2.C);                                     \
                    a20 = ffma2(d, w.x, a20); a21 = ffma2(d, w.y, a21);        \
                    d = pack2(h3.C, h3.C);                                     \
                    a30 = ffma2(d, w.x, a30); a31 = ffma2(d, w.y, a31);        \
                }
                RNN_SUBK(0, x)
                RNN_SUBK(1, y)
                RNN_SUBK(2, z)
                RNN_SUBK(3, w)
#undef RNN_SUBK
            }

            // Partials: Pr[g][row*32 + col]
            float* pg = &Pr[g << 9];
            *reinterpret_cast<ulonglong2*>(&pg[(r0 + 0) * 32 + c0]) = make_ulonglong2(a00, a01);
            *reinterpret_cast<ulonglong2*>(&pg[(r0 + 1) * 32 + c0]) = make_ulonglong2(a10, a11);
            *reinterpret_cast<ulonglong2*>(&pg[(r0 + 2) * 32 + c0]) = make_ulonglong2(a20, a21);
            *reinterpret_cast<ulonglong2*>(&pg[(r0 + 3) * 32 + c0]) = make_ulonglong2(a30, a31);
            __syncthreads();      // the ONLY block barrier per step

            // 16-way reduction: thread tid sums Pr[gg][tid]
#pragma unroll
            for (int gg = 0; gg < 16; ++gg)
                s += Pr[(gg << 9) + tid];
        }
        // t == 0: h_{-1}=0 -> output = tanh(xp)

        float o = tanhf(s + xv);
        size_t hoff = (size_t)(m0 + er) * H_ + n0 + ec;
        __stcg(&hn[hoff], o);

        // Release THIS warp's arrival for step t (covers all 32 lanes' stores
        // via the syncwarp memory-ordering, then a fused release-reduction).
        __syncwarp();
        if (lane == 0 && t != S_ - 1)
            asm volatile("red.release.gpu.global.add.u32 [%0], %1;"
                         :: "l"(&g_flags[fi]), "r"(1u) : "memory");

        if (seqOut)
            __stcg(&seqOut[((size_t)(m0 + er) * S_ + t) * H_ + n0 + ec], o);

        if (t != S_ - 1)   // prefetch next xp (hides under the poll)
            xv = __ldg(xrow + (size_t)(t + 1) * H_);
    }
}

// ---------------------------------------------------------------------------
// C[M,N] = A[M,K] @ W[N,K]^T + b1[N] + b2[N]
// 128x64 tile, BK=16, 256 threads, 8x4 microtile, packed f32x2 FMAs.
// ---------------------------------------------------------------------------
__global__ __launch_bounds__(256) void sgemm_bias(
    const float* __restrict__ A, const float* __restrict__ W,
    const float* __restrict__ b1, const float* __restrict__ b2,
    float* __restrict__ C, int M, int N, int K)
{
    __shared__ float As[16][132];
    __shared__ float Wt[16][68];
    const int tid = threadIdx.x;
    const int tx = tid & 15, ty = tid >> 4;
    const int m0 = blockIdx.x * 128, n0 = blockIdx.y * 64;

    unsigned long long acc[8][2];
#pragma unroll
    for (int i = 0; i < 8; ++i) { acc[i][0] = 0; acc[i][1] = 0; }

    for (int k0 = 0; k0 < K; k0 += 16) {
#pragma unroll
        for (int j = 0; j < 2; ++j) {
            int i  = tid + (j << 8);
            int lr = i >> 2;
            int lk = (i & 3) << 2;
            float4 v = *reinterpret_cast<const float4*>(&A[(size_t)(m0 + lr) * K + k0 + lk]);
            As[lk + 0][lr] = v.x; As[lk + 1][lr] = v.y;
            As[lk + 2][lr] = v.z; As[lk + 3][lr] = v.w;
        }
        {
            int ln = tid >> 2;
            int lk = (tid & 3) << 2;
            float4 v = *reinterpret_cast<const float4*>(&W[(size_t)(n0 + ln) * K + k0 + lk]);
            Wt[lk + 0][ln] = v.x; Wt[lk + 1][ln] = v.y;
            Wt[lk + 2][ln] = v.z; Wt[lk + 3][ln] = v.w;
        }
        __syncthreads();
#pragma unroll
        for (int kk = 0; kk < 16; ++kk) {
            float4 x0 = *reinterpret_cast<const float4*>(&As[kk][ty << 3]);
            float4 x1 = *reinterpret_cast<const float4*>(&As[kk][(ty << 3) + 4]);
            const ulonglong2 w = *reinterpret_cast<const ulonglong2*>(&Wt[kk][tx << 2]);
            unsigned long long d;
#define GEMM_ROW(i, av, C)                                                     \
            d = pack2(av.C, av.C);                                             \
            acc[i][0] = ffma2(d, w.x, acc[i][0]);                              \
            acc[i][1] = ffma2(d, w.y, acc[i][1]);
            GEMM_ROW(0, x0, x) GEMM_ROW(1, x0, y) GEMM_ROW(2, x0, z) GEMM_ROW(3, x0, w)
            GEMM_ROW(4, x1, x) GEMM_ROW(5, x1, y) GEMM_ROW(6, x1, z) GEMM_ROW(7, x1, w)
#undef GEMM_ROW
        }
        __syncthreads();
    }

    const int n = n0 + (tx << 2);
    unsigned long long bb0 = pack2(b1[n + 0] + b2[n + 0], b1[n + 1] + b2[n + 1]);
    unsigned long long bb1 = pack2(b1[n + 2] + b2[n + 2], b1[n + 3] + b2[n + 3]);
#pragma unroll
    for (int i = 0; i < 8; ++i) {
        int m = m0 + (ty << 3) + i;
        *reinterpret_cast<ulonglong2*>(&C[(size_t)m * N + n]) =
            make_ulonglong2(fadd2(acc[i][0], bb0), fadd2(acc[i][1], bb1));
    }
}

// ---------------------------------------------------------------------------
// logits = h_last @ W_out^T + b_out; out = log_softmax(logits)
// ---------------------------------------------------------------------------
__global__ __launch_bounds__(256) void out_kernel(
    const float* __restrict__ h, const float* __restrict__ Wout,
    const float* __restrict__ bout, float* __restrict__ out)
{
    __shared__ float hs[H_];
    __shared__ float logits[C_];
    __shared__ float red[8];
    int b = blockIdx.x;
    int tid = threadIdx.x;
    int warp = tid >> 5, lane = tid & 31;

    for (int k = tid; k < H_; k += 256) hs[k] = h[(size_t)b * H_ + k];
    __syncthreads();

    for (int c = warp; c < C_; c += 8) {
        const float* wr = Wout + (size_t)c * H_;
        float s = 0.f;
#pragma unroll
        for (int k = lane; k < H_; k += 32) s += hs[k] * wr[k];
#pragma unroll
        for (int off = 16; off > 0; off >>= 1) s += __shfl_down_sync(0xffffffffu, s, off);
        if (lane == 0) logits[c] = s + bout[c];
    }
    __syncthreads();

    float mx = -1e30f;
    for (int c = tid; c < C_; c += 256) mx = fmaxf(mx, logits[c]);
#pragma unroll
    for (int off = 16; off > 0; off >>= 1) mx = fmaxf(mx, __shfl_down_sync(0xffffffffu, mx, off));
    if (lane == 0) red[warp] = mx;
    __syncthreads();
    if (tid == 0) {
        float m2 = red[0];
        for (int i = 1; i < 8; i++) m2 = fmaxf(m2, red[i]);
        red[0] = m2;
    }
    __syncthreads();
    mx = red[0];
    __syncthreads();

    float se = 0.f;
    for (int c = tid; c < C_; c += 256) se += expf(logits[c] - mx);
#pragma unroll
    for (int off = 16; off > 0; off >>= 1) se += __shfl_down_sync(0xffffffffu, se, off);
    if (lane == 0) red[warp] = se;
    __syncthreads();
    if (tid == 0) {
        float s2 = 0.f;
        for (int i = 0; i < 8; i++) s2 += red[i];
        red[0] = logf(s2);
    }
    __syncthreads();
    float lse = red[0];

    for (int c = tid; c < C_; c += 256)
        out[(size_t)b * C_ + c] = logits[c] - mx - lse;
}

extern "C" void kernel_launch(void* const* d_in, const int* in_sizes, int n_in,
                              void* d_out, int out_size)
{
    (void)in_sizes; (void)n_in; (void)out_size;
    const float* x     = (const float*)d_in[0];
    const float* W_ih0 = (const float*)d_in[1];
    const float* W_hh0 = (const float*)d_in[2];
    const float* b_ih0 = (const float*)d_in[3];
    const float* b_hh0 = (const float*)d_in[4];
    const float* W_ih1 = (const float*)d_in[5];
    const float* W_hh1 = (const float*)d_in[6];
    const float* b_ih1 = (const float*)d_in[7];
    const float* b_hh1 = (const float*)d_in[8];
    const float* W_out = (const float*)d_in[9];
    const float* b_out = (const float*)d_in[10];
    float* out = (float*)d_out;

    float *xp, *seq, *hbuf;
    cudaGetSymbolAddress((void**)&xp,   g_xp);
    cudaGetSymbolAddress((void**)&seq,  g_seq);
    cudaGetSymbolAddress((void**)&hbuf, g_h);
    float* hA = hbuf;
    float* hB = hbuf + B_ * H_;

    const int smem_bytes =
        (512 * 32 + NWRP * 16 * HSPW + 2 * NWRP * 512) * 4;  // 167936
    cudaFuncSetAttribute(rnn_layer_kernel,
                         cudaFuncAttributeMaxDynamicSharedMemorySize, smem_bytes);

    dim3 gg(B_ * S_ / 128, H_ / 64);  // (512, 8)
    dim3 gr(B_ / 16, H_ / 32);        // (8, 16) = 128 persistent blocks

    // layer 0
    sgemm_bias<<<gg, 256>>>(x, W_ih0, b_ih0, b_hh0, xp, B_ * S_, H_, IN_);
    rnn_layer_kernel<<<gr, 512, smem_bytes>>>(xp, W_hh0, hA, hB, seq);

    // layer 1
    sgemm_bias<<<gg, 256>>>(seq, W_ih1, b_ih1, b_hh1, xp, B_ * S_, H_, H_);
    rnn_layer_kernel<<<gr, 512, smem_bytes>>>(xp, W_hh1, hA, hB, nullptr);

    // output head on h_{S-1} (t=511 odd -> final state in hB)
    out_kernel<<<B_, 256>>>(hB, W_out, b_out, out);
}